// round 2
// baseline (speedup 1.0000x reference)
#include <cuda_runtime.h>

#define NXC 512
#define NYC 512
#define PHW 3
#define PP 6            // patch size = 2*PHW
#define BB 128
#define SS 1024

// 1/(sqrt(2)*sigma), sigma=0.92
__device__ __forceinline__ float inv_alpha() { return 1.0f / (1.41421356237309515f * 0.92f); }

__global__ void zero_kernel(float4* __restrict__ out, int n4) {
    int stride = gridDim.x * blockDim.x;
    for (int i = blockIdx.x * blockDim.x + threadIdx.x; i < n4; i += stride)
        out[i] = make_float4(0.f, 0.f, 0.f, 0.f);
}

__global__ void scatter_kernel(const float* __restrict__ z, float* __restrict__ out) {
    int gid = blockIdx.x * blockDim.x + threadIdx.x;
    if (gid >= BB * SS) return;
    int b = gid >> 10;          // source batch
    int s = gid & (SS - 1);     // source index

    // z layout: (B, 2, S) flattened — x at [b, 0, s], y at [b, 1, s]
    float x0 = __ldg(&z[b * 2 * SS + s]);
    float y0 = __ldg(&z[b * 2 * SS + SS + s]);

    int patchx = __float2int_rn(x0) - PHW;
    int patchy = __float2int_rn(y0) - PHW;
    float x0p = x0 - (float)patchx;
    float y0p = y0 - (float)patchy;

    // validity (always true for this input range, kept for correctness)
    if (patchx < 0 || patchx >= NXC - PP || patchy < 0 || patchy >= NYC - PP) return;

    const float ia = inv_alpha();

    // erf prefix evaluations at k - 0.5 for k = 0..6
    float ex[PP + 1], ey[PP + 1];
#pragma unroll
    for (int k = 0; k <= PP; k++) {
        float kk = (float)k - 0.5f;
        ex[k] = erff((kk - x0p) * ia);
        ey[k] = erff((kk - y0p) * ia);
    }

    float lx[PP], ly[PP];
#pragma unroll
    for (int k = 0; k < PP; k++) {
        lx[k] = 0.5f * (ex[k + 1] - ex[k]);
        ly[k] = 0.5f * (ey[k + 1] - ey[k]);
    }

    const float i0 = 1000.0f;   // eta * N0 * texp
    float* __restrict__ img = out + (size_t)b * NXC * NYC;

#pragma unroll
    for (int i = 0; i < PP; i++) {
        float pre = i0 * lx[i];
        int base = (patchx + i) * NYC + patchy;
#pragma unroll
        for (int j = 0; j < PP; j++) {
            atomicAdd(&img[base + j], pre * ly[j]);   // no return -> REDG
        }
    }
}

extern "C" void kernel_launch(void* const* d_in, const int* in_sizes, int n_in,
                              void* d_out, int out_size) {
    const float* z = (const float*)d_in[0];
    float* out = (float*)d_out;

    int n4 = out_size / 4;                       // 33.5M floats -> 8.4M float4
    int zblocks = (n4 + 511) / 512;
    if (zblocks > 8192) zblocks = 8192;          // grid-stride handles the rest
    zero_kernel<<<zblocks, 512>>>((float4*)out, n4);

    int nsrc = BB * SS;
    int sblocks = (nsrc + 255) / 256;
    scatter_kernel<<<sblocks, 256>>>(z, out);
}